// round 13
// baseline (speedup 1.0000x reference)
#include <cuda_runtime.h>
#include <cuda_fp16.h>
#include <math.h>

#define BB 8
#define SEQL 256
#define MEML 768
#define TOT 1024
#define DIMM 512
#define NH 8
#define DH 64
#define INNERD 512
#define CTXL 1024
#define NOCTL 11

// ---------------- fp16 split helpers ----------------
__device__ __forceinline__ void split2h(float x, float y, __half2& h, __half2& l) {
    h = __floats2half2_rn(x, y);
    float2 f = __half22float2(h);
    l = __floats2half2_rn(x - f.x, y - f.y);
}
__device__ __forceinline__ void split1h(float x, __half& h, __half& l) {
    h = __float2half_rn(x);
    l = __float2half_rn(x - __half2float(h));
}
__device__ __forceinline__ void mma16816(float* c, const unsigned* a, const unsigned* b) {
    asm volatile(
        "mma.sync.aligned.m16n8k16.row.col.f32.f16.f16.f32 "
        "{%0,%1,%2,%3}, {%4,%5,%6,%7}, {%8,%9}, {%0,%1,%2,%3};\n"
        : "+f"(c[0]), "+f"(c[1]), "+f"(c[2]), "+f"(c[3])
        : "r"(a[0]), "r"(a[1]), "r"(a[2]), "r"(a[3]), "r"(b[0]), "r"(b[1]));
}
__device__ __forceinline__ void ldsm4(unsigned* r, const __half* p) {
    unsigned a = (unsigned)__cvta_generic_to_shared(p);
    asm volatile("ldmatrix.sync.aligned.m8n8.x4.shared.b16 {%0,%1,%2,%3}, [%4];"
        : "=r"(r[0]), "=r"(r[1]), "=r"(r[2]), "=r"(r[3]) : "r"(a));
}
// ---------------- cp.async helpers ----------------
__device__ __forceinline__ void cp16(void* dst, const void* src) {
    unsigned d = (unsigned)__cvta_generic_to_shared(dst);
    asm volatile("cp.async.cg.shared.global [%0], [%1], 16;" :: "r"(d), "l"(src));
}
__device__ __forceinline__ void cp_commit() {
    asm volatile("cp.async.commit_group;");
}
template<int N> __device__ __forceinline__ void cp_wait() {
    asm volatile("cp.async.wait_group %0;" :: "n"(N));
}

// ---------------- scratch (device globals) ----------------
__device__ __half g_Inh[8192*512];                       // concat(memory,x) hi
__device__ __half g_WqTh[1536*512], g_WqTl[1536*512];    // W_qkv^T split (B operand)
__device__ __half g_WoTh[512*512],  g_WoTl[512*512];     // W_out^T split (B operand)
__device__ __half g_QUh[BB*NH*SEQL*DH];                  // A operand: hi only
__device__ __half g_QVh[BB*NH*SEQL*DH];                  // A operand: hi only
__device__ __half g_Kh [BB*NH*TOT*DH],  g_Kl [BB*NH*TOT*DH];   // B operand: split
__device__ __half g_VTh[BB*NH*DH*TOT],  g_VTl[BB*NH*DH*TOT];   // B operand: split
__device__ __half g_Krelh[NH*CTXL*DH],  g_Krell[NH*CTXL*DH];   // B operand: split
__device__ __half g_AOh[BB*SEQL*INNERD];                 // A operand: hi only
__device__ __half g_BDs[BB*NH*SEQL*TOT];   // BD pre-shifted, fp16 (|BD|~1, abs err ~5e-4)
// split-KV partials: [split][bh][n4][row(64)] (+ [col(64)] for O)
__device__ float  g_Opart[2*64*4*64*64];   // 16.8 MB
__device__ float  g_Mpart[2*64*4*64];
__device__ float  g_Lpart[2*64*4*64];

// =====================================================================
// pre_in: hi-only split of concat(memory, x)  (NO smem — full occupancy)
// =====================================================================
__global__ __launch_bounds__(256) void pre_in_kernel(
    const float* __restrict__ x, const float* __restrict__ mm)
{
    int fid = blockIdx.x*256 + threadIdx.x;
    int gr = fid >> 7;
    int c4 = fid & 127;
    int b = gr >> 10, pos = gr & 1023;
    const float* src = (pos < MEML)
        ? (mm + ((size_t)(b*MEML + pos))*DIMM)
        : (x  + ((size_t)(b*SEQL + pos - MEML))*DIMM);
    float4 v = *(const float4*)(src + c4*4);
    size_t idx = (size_t)gr*512 + c4*4;
    *(__half2*)&g_Inh[idx]   = __floats2half2_rn(v.x, v.y);
    *(__half2*)&g_Inh[idx+2] = __floats2half2_rn(v.z, v.w);
}

// =====================================================================
// prep_small: merged pre_w(Wqkv) [0,192) + pre_w(Wout) [192,256)
//           + krel [256,384) (8 s-positions per block, W_rel in smem)
// Only small-count kernels here; occupancy irrelevant; 46KB smem OK.
// =====================================================================
__global__ __launch_bounds__(256) void prep_small_kernel(
    const float* __restrict__ Wqkv, const float* __restrict__ Wout,
    const float* __restrict__ Wrel)
{
    __shared__ __align__(16) float pf[22*512 + 8*22];
    int t = threadIdx.x;
    int blk = blockIdx.x;

    if (blk < 256) {
        const float* src;
        __half *dh, *dl;
        int N, idx;
        if (blk < 192) { idx = blk;       N = 1536; src = Wqkv; dh = g_WqTh; dl = g_WqTl; }
        else           { idx = blk - 192; N = 512;  src = Wout; dh = g_WoTh; dl = g_WoTl; }
        int nblk = N >> 6;
        int n0 = (idx % nblk)*64;
        int k0 = (idx / nblk)*64;
        float* T = pf;   // [64][68]
#pragma unroll
        for (int i = 0; i < 4; i++) {
            int fid = t + i*256;
            int kr = fid >> 4, c4 = fid & 15;
            *(float4*)&T[kr*68 + c4*4] = *(const float4*)(src + (size_t)(k0+kr)*N + n0 + c4*4);
        }
        __syncthreads();
#pragma unroll
        for (int i = 0; i < 8; i++) {
            int id2 = t + i*256;
            int n = id2 >> 5, kk = (id2 & 31)*2;
            __half2 h, l;
            split2h(T[kk*68 + n], T[(kk+1)*68 + n], h, l);
            size_t o = (size_t)(n0+n)*512 + k0 + kk;
            *(__half2*)&dh[o] = h; *(__half2*)&dl[o] = l;
        }
        return;
    }

    // ---- krel part ----
    {
        int s0 = (blk - 256) * 8;
        float* Wr = pf;             // [22][512]
        float* R  = pf + 22*512;    // [8][22]
#pragma unroll
        for (int i = 0; i < 44; i++)
            Wr[t + i*256] = Wrel[t + i*256];
        for (int idx = t; idx < 8*22; idx += 256) {
            int si = idx / 22, j = idx % 22;
            int jj = (j < NOCTL) ? j : j - NOCTL;
            float mult = exp2f((float)(jj - (NOCTL-1))) * 3.14159265358979323846f;
            float arg = (float)(s0 + si) * mult;
            R[idx] = (j < NOCTL) ? sinf(arg) : cosf(arg);
        }
        __syncthreads();
        int t2 = t*2;
        int h = t2 >> 6, d = t2 & 63;
#pragma unroll
        for (int si = 0; si < 8; si++) {
            float a0 = 0.f, a1 = 0.f;
#pragma unroll
            for (int j = 0; j < 22; j++) {
                float r = R[si*22 + j];
                a0 += r * Wr[j*512 + t2];
                a1 += r * Wr[j*512 + t2 + 1];
            }
            __half h0, l0, h1, l1;
            split1h(a0, h0, l0); split1h(a1, h1, l1);
            size_t idx = ((size_t)h*CTXL + (s0 + si))*DH + d;
            *(__half2*)&g_Krelh[idx] = __halves2half2(h0, h1);
            *(__half2*)&g_Krell[idx] = __halves2half2(l0, l1);
        }
    }
}

// =====================================================================
// GEMM core (k=64): A hi-only, B split -> 2 mma per product
// =====================================================================
__device__ __forceinline__ void gemm_block_k64_A1(
    const __half* Ah, const __half* Bh, const __half* Bl,
    int lane, int wm, int wn, float acc[2][8][4])
{
    int arow = (lane & 7) + ((lane >> 3) & 1)*8;
    int acol = (lane >> 4)*8;
    int brow = (lane & 7) + (lane >> 4)*8;
    int bcol = ((lane >> 3) & 1)*8;
#pragma unroll
    for (int kb = 0; kb < 64; kb += 16) {
        unsigned ah[2][4];
#pragma unroll
        for (int f = 0; f < 2; f++)
            ldsm4(ah[f], &Ah[(wm + f*16 + arow)*72 + kb + acol]);
#pragma unroll
        for (int jp = 0; jp < 4; jp++) {
            unsigned bh[4], bl[4];
            ldsm4(bh, &Bh[(wn + jp*16 + brow)*72 + kb + bcol]);
            ldsm4(bl, &Bl[(wn + jp*16 + brow)*72 + kb + bcol]);
#pragma unroll
            for (int f = 0; f < 2; f++) {
                mma16816(acc[f][2*jp],   ah[f], bh);
                mma16816(acc[f][2*jp],   ah[f], bl);
                mma16816(acc[f][2*jp+1], ah[f], bh+2);
                mma16816(acc[f][2*jp+1], ah[f], bl+2);
            }
        }
    }
}

#define STAGE_HALVES (3*128*72)
#define GEMM_SMEM_BYTES (2*STAGE_HALVES*2)      // 110592 B
#define BD_SMEM_BYTES (STAGE_HALVES*2)

// =====================================================================
// QKV projection: A = In hi, B = Wqkv split. Double-buffered, single sync.
// =====================================================================
__device__ __forceinline__ void qkv_load_stage(__half* S, int r0, int c0, int k0, int t)
{
    __half* Ah = S;
    __half* Bh = Ah + 128*72;
    __half* Bl = Bh + 128*72;
#pragma unroll
    for (int i = 0; i < 4; i++) {
        int fid = t + i*256;
        int row = fid >> 3, c8 = fid & 7;
        cp16(&Ah[row*72 + c8*8], &g_Inh [(size_t)(r0+row)*512 + k0 + c8*8]);
        cp16(&Bh[row*72 + c8*8], &g_WqTh[(size_t)(c0+row)*512 + k0 + c8*8]);
        cp16(&Bl[row*72 + c8*8], &g_WqTl[(size_t)(c0+row)*512 + k0 + c8*8]);
    }
}

__global__ __launch_bounds__(256) void qkv_kernel(
    const float* __restrict__ u_emb, const float* __restrict__ v_emb)
{
    extern __shared__ __half smh[];
    int t = threadIdx.x, lane = t & 31, wid = t >> 5;
    int wm = (wid & 3)*32, wn = (wid >> 2)*64;
    int r0 = blockIdx.y*128, c0 = blockIdx.x*128;
    int which0 = c0 >> 9;
    if (which0 == 0 && (r0 & 1023) < MEML) return;

    float acc[2][8][4];
#pragma unroll
    for (int f = 0; f < 2; f++)
#pragma unroll
        for (int j = 0; j < 8; j++)
#pragma unroll
            for (int e = 0; e < 4; e++) acc[f][j][e] = 0.f;

    qkv_load_stage(smh, r0, c0, 0, t);
    cp_commit();
#pragma unroll
    for (int it = 0; it < 8; it++) {
        __half* cur = smh + (it & 1)*STAGE_HALVES;
        cp_wait<0>();
        __syncthreads();
        if (it < 7) {
            qkv_load_stage(smh + ((it+1) & 1)*STAGE_HALVES, r0, c0, (it+1)*64, t);
            cp_commit();
        }
        gemm_block_k64_A1(cur, cur + 128*72, cur + 2*128*72, lane, wm, wn, acc);
    }

    if (which0 == 2) {
        __syncthreads();
        __half* Th = smh;                 // [col 128][row 128] stride 136
        __half* Tl = smh + 128*136;
#pragma unroll
        for (int f = 0; f < 2; f++)
#pragma unroll
            for (int j = 0; j < 8; j++)
#pragma unroll
                for (int ii = 0; ii < 2; ii++) {
                    int row = wm + f*16 + (lane >> 2) + ii*8;
                    int colL = wn + j*8 + 2*(lane & 3);
                    float v0 = acc[f][j][2*ii], v1 = acc[f][j][2*ii+1];
                    __half h0, l0, h1, l1;
                    split1h(v0, h0, l0); split1h(v1, h1, l1);
                    Th[colL*136 + row] = h0; Th[(colL+1)*136 + row] = h1;
                    Tl[colL*136 + row] = l0; Tl[(colL+1)*136 + row] = l1;
                }
        __syncthreads();
        int b = r0 >> 10, posbase = r0 & 1023;
        int cpr = c0 - 1024;
#pragma unroll
        for (int i = 0; i < 8; i++) {
            int idx = t + i*256;
            int col = idx >> 4, u8 = idx & 15;
            int cc = cpr + col;
            int h = cc >> 6, d = cc & 63;
            size_t o = (((size_t)(b*NH + h))*DH + d)*TOT + posbase + u8*8;
            *(uint4*)&g_VTh[o] = *(const uint4*)&Th[col*136 + u8*8];
            *(uint4*)&g_VTl[o] = *(const uint4*)&Tl[col*136 + u8*8];
        }
        return;
    }

#pragma unroll
    for (int f = 0; f < 2; f++)
#pragma unroll
        for (int j = 0; j < 8; j++)
#pragma unroll
            for (int ii = 0; ii < 2; ii++) {
                int gr = r0 + wm + f*16 + (lane >> 2) + ii*8;
                int gc = c0 + wn + j*8 + 2*(lane & 3);
                float v0 = acc[f][j][2*ii], v1 = acc[f][j][2*ii+1];
                int b = gr >> 10, pos = gr & 1023;
                int cc = gc & 511;
                int h = cc >> 6, d = cc & 63;
                int bh = b*NH + h;
                if (which0 == 1) {
                    __half2 hh, ll; split2h(v0, v1, hh, ll);
                    size_t idx = ((size_t)bh*TOT + pos)*DH + d;
                    *(__half2*)&g_Kh[idx] = hh; *(__half2*)&g_Kl[idx] = ll;
                } else if (pos >= MEML) {
                    int n = pos - MEML;
                    size_t idx = ((size_t)bh*SEQL + n)*DH + d;
                    *(__half2*)&g_QUh[idx] = __floats2half2_rn(v0 + u_emb[d], v1 + u_emb[d+1]);
                    *(__half2*)&g_QVh[idx] = __floats2half2_rn(v0 + v_emb[d], v1 + v_emb[d+1]);
                }
            }
}

// =====================================================================
// bd: A = QV hi, B = Krel split. Stores PRE-SHIFTED fp16 BDs[bh][n][m]
// =====================================================================
__global__ __launch_bounds__(256) void bd_kernel()
{
    extern __shared__ __half smh[];
    __half* Ah = smh;
    __half* Bh = Ah + 128*72;
    __half* Bl = Bh + 128*72;
    int t = threadIdx.x, lane = t & 31, wid = t >> 5;
    int wm = (wid & 3)*32, wn = (wid >> 2)*64;
    int bh = blockIdx.z, h = bh & 7;
    int n0 = blockIdx.y*128, s0 = blockIdx.x*128;
    if (s0 > MEML + n0 + 127) return;

    float acc[2][8][4];
#pragma unroll
    for (int f = 0; f < 2; f++)
#pragma unroll
        for (int j = 0; j < 8; j++)
#pragma unroll
            for (int e = 0; e < 4; e++) acc[f][j][e] = 0.f;

#pragma unroll
    for (int i = 0; i < 4; i++) {
        int fid = t + i*256;
        int row = fid >> 3, c8 = fid & 7;
        cp16(&Ah[row*72 + c8*8], &g_QVh[((size_t)bh*SEQL + n0 + row)*DH + c8*8]);
        cp16(&Bh[row*72 + c8*8], &g_Krelh[((size_t)h*CTXL + s0 + row)*DH + c8*8]);
        cp16(&Bl[row*72 + c8*8], &g_Krell[((size_t)h*CTXL + s0 + row)*DH + c8*8]);
    }
    cp_commit();
    cp_wait<0>();
    __syncthreads();
    gemm_block_k64_A1(Ah, Bh, Bl, lane, wm, wn, acc);

#pragma unroll
    for (int f = 0; f < 2; f++)
#pragma unroll
        for (int j = 0; j < 8; j++)
#pragma unroll
            for (int ii = 0; ii < 2; ii++) {
                int n = n0 + wm + f*16 + (lane >> 2) + ii*8;
                int s = s0 + wn + j*8 + 2*(lane & 3);
                int m = MEML + n - s;
                __half* row = g_BDs + ((size_t)bh*SEQL + n)*TOT;
                if (m >= 0)     row[m]   = __float2half_rn(acc[f][j][2*ii]);
                if (m - 1 >= 0) row[m-1] = __float2half_rn(acc[f][j][2*ii+1]);
            }
}

// =====================================================================
// attn: split-KV flash attention (2 splits). Single KV stage, 55KB smem.
// BD read as fp16 half2.
// =====================================================================
#define ATTN_SMEM_BYTES (6*64*72*2)   // Q, P, Kh, Kl, Vh, Vl = 55296 B

__device__ __forceinline__ void attn_load_kv(
    __half* kv, int bh, int m0, int t)
{
    __half* Kh = kv;
    __half* Kl = Kh + 64*72;
    __half* Vh = Kl + 64*72;
    __half* Vl = Vh + 64*72;
#pragma unroll
    for (int i = 0; i < 4; i++) {
        int fid = t + i*128;
        int row = fid >> 3, c8 = fid & 7;
        cp16(&Kh[row*72 + c8*8], &g_Kh[((size_t)bh*TOT + m0 + row)*DH + c8*8]);
        cp16(&Kl[row*72 + c8*8], &g_Kl[((size_t)bh*TOT + m0 + row)*DH + c8*8]);
        cp16(&Vh[row*72 + c8*8], &g_VTh[((size_t)bh*DH + row)*TOT + m0 + c8*8]);
        cp16(&Vl[row*72 + c8*8], &g_VTl[((size_t)bh*DH + row)*TOT + m0 + c8*8]);
    }
}

__global__ __launch_bounds__(128) void attn_kernel()
{
    extern __shared__ __half smh[];
    __half* Qh = smh;
    __half* Ph = Qh + 64*72;
    __half* KV = Ph + 64*72;
    __half* Kh = KV;
    __half* Kl = Kh + 64*72;
    __half* Vh = Kl + 64*72;
    __half* Vl = Vh + 64*72;

    int t = threadIdx.x, lane = t & 31, wq = t >> 5;
    int bh = blockIdx.y;
    int n0 = blockIdx.x * 64;
    int split = blockIdx.z;

    int nt = (MEML + n0 + 63)/64 + 1;
    int t0 = split ? nt/2 : 0;
    int t1 = split ? nt : nt/2;

    int arow = (lane & 7) + ((lane >> 3) & 1)*8;
    int acol = (lane >> 4)*8;
    int brow = (lane & 7) + (lane >> 4)*8;
    int bcol = ((lane >> 3) & 1)*8;

#pragma unroll
    for (int i = 0; i < 4; i++) {
        int fid = t + i*128;
        int row = fid >> 3, c8 = fid & 7;
        cp16(&Qh[row*72 + c8*8], &g_QUh[((size_t)bh*SEQL + n0 + row)*DH + c8*8]);
    }
    attn_load_kv(KV, bh, t0*64, t);
    cp_commit();

    float O[8][4];
#pragma unroll
    for (int j = 0; j < 8; j++)
#pragma unroll
        for (int e = 0; e < 4; e++) O[j][e] = 0.f;
    float M[2] = {-1e30f, -1e30f}, L[2] = {0.f, 0.f};

    int rl0 = wq*16 + (lane >> 2);
    int c0j = 2*(lane & 3);
    const __half* BDr0 = g_BDs + ((size_t)bh*SEQL + (n0 + rl0))*TOT;
    const __half* BDr1 = BDr0 + 8*(size_t)TOT;
    int lim0 = MEML + n0 + rl0, lim1 = lim0 + 8;

    for (int tile = t0; tile < t1; tile++) {
        int m0 = tile*64;
        cp_wait<0>();
        __syncthreads();

        // prefetch BD strip (fp16 half2, overlaps QK mma)
        float2 bdv[2][8];
#pragma unroll
        for (int j = 0; j < 8; j++) {
            int m = m0 + j*8 + c0j;
            bdv[0][j] = __half22float2(*(const __half2*)&BDr0[m]);
            bdv[1][j] = __half22float2(*(const __half2*)&BDr1[m]);
        }

        // ---- S = Q . K^T  (Q hi; K split) ----
        float S[8][4];
#pragma unroll
        for (int j = 0; j < 8; j++)
#pragma unroll
            for (int e = 0; e < 4; e++) S[j][e] = 0.f;
#pragma unroll
        for (int kb = 0; kb < 64; kb += 16) {
            unsigned ah[4];
            ldsm4(ah, &Qh[(wq*16 + arow)*72 + kb + acol]);
#pragma unroll
            for (int jp = 0; jp < 4; jp++) {
                unsigned bhf[4], blf[4];
                ldsm4(bhf, &Kh[(jp*16 + brow)*72 + kb + bcol]);
                ldsm4(blf, &Kl[(jp*16 + brow)*72 + kb + bcol]);
                mma16816(S[2*jp],   ah, bhf);
                mma16816(S[2*jp],   ah, blf);
                mma16816(S[2*jp+1], ah, bhf+2);
                mma16816(S[2*jp+1], ah, blf+2);
            }
        }

        // ---- BD add + mask + online softmax ----
#pragma unroll
        for (int i = 0; i < 2; i++) {
            int lim = i ? lim1 : lim0;
            float mx = -1e30f;
#pragma unroll
            for (int j = 0; j < 8; j++) {
                int m = m0 + j*8 + c0j;
                float v0 = (m   <= lim) ? (S[j][2*i]   + bdv[i][j].x)*0.125f : -1e30f;
                float v1 = (m+1 <= lim) ? (S[j][2*i+1] + bdv[i][j].y)*0.125f : -1e30f;
                S[j][2*i] = v0; S[j][2*i+1] = v1;
                mx = fmaxf(mx, fmaxf(v0, v1));
            }
            mx = fmaxf(mx, __shfl_xor_sync(0xffffffffu, mx, 1));
            mx = fmaxf(mx, __shfl_xor_sync(0xffffffffu, mx, 2));
            float Mn = fmaxf(M[i], mx);
            float alpha = __expf(M[i] - Mn);
            M[i] = Mn;
            float sum = 0.f;
            int rl = rl0 + 8*i;
#pragma unroll
            for (int j = 0; j < 8; j++) {
                float p0 = __expf(S[j][2*i]   - Mn);
                float p1 = __expf(S[j][2*i+1] - Mn);
                sum += p0 + p1;
                *(__half2*)&Ph[rl*72 + j*8 + c0j] = __floats2half2_rn(p0, p1);
                O[j][2*i] *= alpha; O[j][2*i+1] *= alpha;
            }
            sum += __shfl_xor_sync(0xffffffffu, sum, 1);
            sum += __shfl_xor_sync(0xffffffffu, sum, 2);
            L[i] = L[i]*alpha + sum;
        }
        __syncwarp();

        // ---- O += P . V  (P hi; V split) ----
#pragma unroll
        for (int kb = 0; kb < 64; kb += 16) {
            unsigned ah[4];
            ldsm4(ah, &Ph[(wq*16 + arow)*72 + kb + acol]);
#pragma unroll
            for (int jp = 0; jp < 4; jp++) {
                unsigned bhf[4], blf[4];
                ldsm4(bhf, &Vh[(jp*16 + brow)*72 + kb + bcol]);
                ldsm4(blf, &Vl[(jp*16 + brow)*72 + kb + bcol]);
                mma16816(O[2*jp],   ah, bhf);
                mma16816(O[2*jp],   ah, blf);
                mma16816(O[2*jp+1], ah, bhf+2);
                mma16816(O[2*jp+1], ah, blf+2);
            }
        }

        __syncthreads();   // done reading KV before next load overwrites it
        if (tile + 1 < t1) {
            attn_load_kv(KV, bh, (tile+1)*64, t);
            cp_commit();
        }
    }

    // ---- write unnormalized partials ----
    size_t pbase = (((size_t)split*64 + bh)*4 + (n0 >> 6))*64;
    float* Op = g_Opart + pbase*64;
#pragma unroll
    for (int i = 0; i < 2; i++) {
        int row = rl0 + 8*i;
        if ((lane & 3) == 0) {
            g_Mpart[pbase + row] = M[i];
            g_Lpart[pbase + row] = L[i];
        }
#pragma unroll
        for (int j = 0; j < 8; j++) {
            int col = j*8 + c0j;
            *(float2*)&Op[(size_t)row*64 + col] = make_float2(O[j][2*i], O[j][2*i+1]);
        }
    }
}

// =====================================================================
// attn_comb: merge 2 split-KV partials -> g_AOh
// =====================================================================
__global__ __launch_bounds__(256) void attn_comb_kernel()
{
    __shared__ float f0[64], f1[64];
    int t = threadIdx.x;
    int n4 = blockIdx.x;     // 0..3
    int bh = blockIdx.y;     // 0..63
    int b = bh >> 3, h = bh & 7;
    size_t p0 = (((size_t)0*64 + bh)*4 + n4)*64;
    size_t p1 = (((size_t)1*64 + bh)*4 + n4)*64;

    if (t < 64) {
        float M0 = g_Mpart[p0 + t], M1 = g_Mpart[p1 + t];
        float L0 = g_Lpart[p0 + t], L1 = g_Lpart[p1 + t];
        float Mn = fmaxf(M0, M1);
        float a0 = __expf(M0 - Mn), a1 = __expf(M1 - Mn);
        float L = L0*a0 + L1*a1;
        f0[t] = a0 / L;
        f1[t] = a1 / L;
    }
    __syncthreads();

    const float* O0 = g_Opart + p0*64;
    const float* O1 = g_Opart + p1*64;
#pragma unroll
    for (int k = 0; k < 8; k++) {
        int idx = t + k*256;          // 2048 half2 units: 64 rows x 32
        int row = idx >> 5;
        int c2 = (idx & 31)*2;
        float2 a = *(const float2*)&O0[(size_t)row*64 + c2];
        float2 bpt = *(const float2*)&O1[(size_t)row*64 + c2];
        float o0 = a.x*f0[row] + bpt.x*f1[row];
        float o1 = a.y*f0[row] + bpt.y*f1[row];
        size_t oidx = ((size_t)(b*SEQL + n4*64 + row))*INNERD + h*DH + c2;
        *(__half2*)&g_AOh[oidx] = __floats2half2_rn(o0, o1);
    }
}

// =====================================================================
// out: A = AO hi, B = Wout split. 128x128 tile, double-buffered, single sync.
// =====================================================================
__device__ __forceinline__ void out_load_stage(__half* S, int r0, int c0, int k0, int t)
{
    __half* Ah = S;
    __half* Bh = Ah + 128*72;
    __half* Bl = Bh + 128*72;
#pragma unroll
    for (int i = 0; i < 4; i++) {
        int fid = t + i*256;
        int row = fid >> 3, c8 = fid & 7;
        cp16(&Ah[row*72 + c8*8], &g_AOh [(size_t)(r0+row)*512 + k0 + c8*8]);
        cp16(&Bh[row*72 + c8*8], &g_WoTh[(size_t)(c0+row)*512 + k0 + c8*8]);
        cp16(&Bl[row*72 + c8*8], &g_WoTl[(size_t)(c0+row)*512 + k0 + c8*8]);
    }
}

__global__ __launch_bounds__(256) void out_kernel(
    const float* __restrict__ bias, float* __restrict__ out)
{
    extern __shared__ __half smh[];
    int t = threadIdx.x, lane = t & 31, wid = t >> 5;
    int wm = (wid & 3)*32, wn = (wid >> 2)*64;
    int r0 = blockIdx.y*128, c0 = blockIdx.x*128;

    float acc[2][8][4];
#pragma unroll
    for (int f = 0; f < 2; f++)
#pragma unroll
        for (int j = 0; j < 8; j++)
#pragma unroll
            for (int e = 0; e < 4; e++) acc[f][j][e] = 0.f;

    out_load_stage(smh, r0, c0, 0, t);
    cp_commit();
#pragma unroll
    for (int it = 0; it < 8; it++) {
        __half* cur = smh + (it & 1)*STAGE_HALVES;
        cp_wait<0>();
        __syncthreads();
        if (it < 7) {
            out_load_stage(smh + ((it+1) & 1)*STAGE_HALVES, r0, c0, (it+1)*64, t);
            cp_commit();
        }
        gemm_block_k64_A1(cur, cur + 128*72, cur + 2*128*72, lane, wm, wn, acc);
    }

#pragma unroll
    for (int f = 0; f < 2; f++)
#pragma unroll
        for (int j = 0; j < 8; j++)
#pragma unroll
            for (int ii = 0; ii < 2; ii++) {
                int gr = r0 + wm + f*16 + (lane >> 2) + ii*8;
                int gc = c0 + wn + j*8 + 2*(lane & 3);
                *(float2*)&out[(size_t)gr*DIMM + gc] =
                    make_float2(acc[f][j][2*ii] + bias[gc], acc[f][j][2*ii+1] + bias[gc+1]);
            }
}

// =====================================================================
extern "C" void kernel_launch(void* const* d_in, const int* in_sizes, int n_in,
                              void* d_out, int out_size)
{
    const float* x      = (const float*)d_in[0];
    const float* memory = (const float*)d_in[1];
    const float* Wqkv   = (const float*)d_in[2];
    const float* Wrel   = (const float*)d_in[3];
    const float* Wout   = (const float*)d_in[4];
    const float* bout   = (const float*)d_in[5];
    const float* u_emb  = (const float*)d_in[6];
    const float* v_emb  = (const float*)d_in[7];
    float* out = (float*)d_out;
    (void)in_sizes; (void)n_in; (void)out_size;

    cudaFuncSetAttribute(qkv_kernel,  cudaFuncAttributeMaxDynamicSharedMemorySize, GEMM_SMEM_BYTES);
    cudaFuncSetAttribute(bd_kernel,   cudaFuncAttributeMaxDynamicSharedMemorySize, BD_SMEM_BYTES);
    cudaFuncSetAttribute(out_kernel,  cudaFuncAttributeMaxDynamicSharedMemorySize, GEMM_SMEM_BYTES);
    cudaFuncSetAttribute(attn_kernel, cudaFuncAttributeMaxDynamicSharedMemorySize, ATTN_SMEM_BYTES);

    pre_in_kernel<<<8192*512/4/256, 256>>>(x, memory);
    prep_small_kernel<<<384, 256>>>(Wqkv, Wout, Wrel);
    qkv_kernel<<<dim3(1536/128, 8192/128), 256, GEMM_SMEM_BYTES>>>(u_emb, v_emb);
    bd_kernel<<<dim3(CTXL/128, SEQL/128, BB*NH), 256, BD_SMEM_BYTES>>>();
    attn_kernel<<<dim3(SEQL/64, BB*NH, 2), 128, ATTN_SMEM_BYTES>>>();
    attn_comb_kernel<<<dim3(SEQL/64, BB*NH), 256>>>();
    out_kernel<<<dim3(DIMM/128, 2048/128), 256, GEMM_SMEM_BYTES>>>(bout, out);
}

// round 14
// speedup vs baseline: 1.0935x; 1.0935x over previous
#include <cuda_runtime.h>
#include <cuda_fp16.h>
#include <math.h>

#define BB 8
#define SEQL 256
#define MEML 768
#define TOT 1024
#define DIMM 512
#define NH 8
#define DH 64
#define INNERD 512
#define CTXL 1024
#define NOCTL 11

// ---------------- fp16 split helpers ----------------
__device__ __forceinline__ void split2h(float x, float y, __half2& h, __half2& l) {
    h = __floats2half2_rn(x, y);
    float2 f = __half22float2(h);
    l = __floats2half2_rn(x - f.x, y - f.y);
}
__device__ __forceinline__ void split1h(float x, __half& h, __half& l) {
    h = __float2half_rn(x);
    l = __float2half_rn(x - __half2float(h));
}
__device__ __forceinline__ void mma16816(float* c, const unsigned* a, const unsigned* b) {
    asm volatile(
        "mma.sync.aligned.m16n8k16.row.col.f32.f16.f16.f32 "
        "{%0,%1,%2,%3}, {%4,%5,%6,%7}, {%8,%9}, {%0,%1,%2,%3};\n"
        : "+f"(c[0]), "+f"(c[1]), "+f"(c[2]), "+f"(c[3])
        : "r"(a[0]), "r"(a[1]), "r"(a[2]), "r"(a[3]), "r"(b[0]), "r"(b[1]));
}
__device__ __forceinline__ void ldsm4(unsigned* r, const __half* p) {
    unsigned a = (unsigned)__cvta_generic_to_shared(p);
    asm volatile("ldmatrix.sync.aligned.m8n8.x4.shared.b16 {%0,%1,%2,%3}, [%4];"
        : "=r"(r[0]), "=r"(r[1]), "=r"(r[2]), "=r"(r[3]) : "r"(a));
}
// ---------------- cp.async helpers ----------------
__device__ __forceinline__ void cp16(void* dst, const void* src) {
    unsigned d = (unsigned)__cvta_generic_to_shared(dst);
    asm volatile("cp.async.cg.shared.global [%0], [%1], 16;" :: "r"(d), "l"(src));
}
__device__ __forceinline__ void cp_commit() {
    asm volatile("cp.async.commit_group;");
}
template<int N> __device__ __forceinline__ void cp_wait() {
    asm volatile("cp.async.wait_group %0;" :: "n"(N));
}

// ---------------- scratch (device globals) ----------------
__device__ __half g_Inh[8192*512];                       // concat(memory,x) hi
__device__ __half g_WqTh[1536*512], g_WqTl[1536*512];    // W_qkv^T split (B operand)
__device__ __half g_WoTh[512*512],  g_WoTl[512*512];     // W_out^T split (B operand)
__device__ __half g_QUh[BB*NH*SEQL*DH];                  // A operand: hi only
__device__ __half g_QVh[BB*NH*SEQL*DH];                  // A operand: hi only
__device__ __half g_Kh [BB*NH*TOT*DH],  g_Kl [BB*NH*TOT*DH];   // B operand: split
__device__ __half g_VTh[BB*NH*DH*TOT],  g_VTl[BB*NH*DH*TOT];   // B operand: split
__device__ __half g_Krelh[NH*CTXL*DH],  g_Krell[NH*CTXL*DH];   // B operand: split
__device__ __half g_AOh[BB*SEQL*INNERD];                 // A operand: hi only
__device__ __half g_BDs[BB*NH*SEQL*TOT];   // BD pre-shifted, fp16
// split-KV partials
__device__ float  g_Opart[2*64*4*64*64];
__device__ float  g_Mpart[2*64*4*64];
__device__ float  g_Lpart[2*64*4*64];

// =====================================================================
// pre_in: hi-only fp16 of concat(memory, x)  (no smem, full occupancy)
// =====================================================================
__global__ __launch_bounds__(256) void pre_in_kernel(
    const float* __restrict__ x, const float* __restrict__ mm)
{
    int fid = blockIdx.x*256 + threadIdx.x;
    int gr = fid >> 7;
    int c4 = fid & 127;
    int b = gr >> 10, pos = gr & 1023;
    const float* src = (pos < MEML)
        ? (mm + ((size_t)(b*MEML + pos))*DIMM)
        : (x  + ((size_t)(b*SEQL + pos - MEML))*DIMM);
    float4 v = *(const float4*)(src + c4*4);
    size_t idx = (size_t)gr*512 + c4*4;
    *(__half2*)&g_Inh[idx]   = __floats2half2_rn(v.x, v.y);
    *(__half2*)&g_Inh[idx+2] = __floats2half2_rn(v.z, v.w);
}

// =====================================================================
// prep_small: merged pre_w(Wqkv) [0,192) + pre_w(Wout) [192,256) + krel [256,384)
// =====================================================================
__global__ __launch_bounds__(256) void prep_small_kernel(
    const float* __restrict__ Wqkv, const float* __restrict__ Wout,
    const float* __restrict__ Wrel)
{
    __shared__ __align__(16) float pf[22*512 + 8*22];
    int t = threadIdx.x;
    int blk = blockIdx.x;

    if (blk < 256) {
        const float* src;
        __half *dh, *dl;
        int N, idx;
        if (blk < 192) { idx = blk;       N = 1536; src = Wqkv; dh = g_WqTh; dl = g_WqTl; }
        else           { idx = blk - 192; N = 512;  src = Wout; dh = g_WoTh; dl = g_WoTl; }
        int nblk = N >> 6;
        int n0 = (idx % nblk)*64;
        int k0 = (idx / nblk)*64;
        float* T = pf;
#pragma unroll
        for (int i = 0; i < 4; i++) {
            int fid = t + i*256;
            int kr = fid >> 4, c4 = fid & 15;
            *(float4*)&T[kr*68 + c4*4] = *(const float4*)(src + (size_t)(k0+kr)*N + n0 + c4*4);
        }
        __syncthreads();
#pragma unroll
        for (int i = 0; i < 8; i++) {
            int id2 = t + i*256;
            int n = id2 >> 5, kk = (id2 & 31)*2;
            __half2 h, l;
            split2h(T[kk*68 + n], T[(kk+1)*68 + n], h, l);
            size_t o = (size_t)(n0+n)*512 + k0 + kk;
            *(__half2*)&dh[o] = h; *(__half2*)&dl[o] = l;
        }
        return;
    }

    {
        int s0 = (blk - 256) * 8;
        float* Wr = pf;
        float* R  = pf + 22*512;
#pragma unroll
        for (int i = 0; i < 44; i++)
            Wr[t + i*256] = Wrel[t + i*256];
        for (int idx = t; idx < 8*22; idx += 256) {
            int si = idx / 22, j = idx % 22;
            int jj = (j < NOCTL) ? j : j - NOCTL;
            float mult = exp2f((float)(jj - (NOCTL-1))) * 3.14159265358979323846f;
            float arg = (float)(s0 + si) * mult;
            R[idx] = (j < NOCTL) ? sinf(arg) : cosf(arg);
        }
        __syncthreads();
        int t2 = t*2;
        int h = t2 >> 6, d = t2 & 63;
#pragma unroll
        for (int si = 0; si < 8; si++) {
            float a0 = 0.f, a1 = 0.f;
#pragma unroll
            for (int j = 0; j < 22; j++) {
                float r = R[si*22 + j];
                a0 += r * Wr[j*512 + t2];
                a1 += r * Wr[j*512 + t2 + 1];
            }
            __half h0, l0, h1, l1;
            split1h(a0, h0, l0); split1h(a1, h1, l1);
            size_t idx = ((size_t)h*CTXL + (s0 + si))*DH + d;
            *(__half2*)&g_Krelh[idx] = __halves2half2(h0, h1);
            *(__half2*)&g_Krell[idx] = __halves2half2(l0, l1);
        }
    }
}

// =====================================================================
// GEMM core (k=64): A hi-only, B split -> 2 mma per product
// =====================================================================
__device__ __forceinline__ void gemm_block_k64_A1(
    const __half* Ah, const __half* Bh, const __half* Bl,
    int lane, int wm, int wn, float acc[2][8][4])
{
    int arow = (lane & 7) + ((lane >> 3) & 1)*8;
    int acol = (lane >> 4)*8;
    int brow = (lane & 7) + (lane >> 4)*8;
    int bcol = ((lane >> 3) & 1)*8;
#pragma unroll
    for (int kb = 0; kb < 64; kb += 16) {
        unsigned ah[2][4];
#pragma unroll
        for (int f = 0; f < 2; f++)
            ldsm4(ah[f], &Ah[(wm + f*16 + arow)*72 + kb + acol]);
#pragma unroll
        for (int jp = 0; jp < 4; jp++) {
            unsigned bh[4], bl[4];
            ldsm4(bh, &Bh[(wn + jp*16 + brow)*72 + kb + bcol]);
            ldsm4(bl, &Bl[(wn + jp*16 + brow)*72 + kb + bcol]);
#pragma unroll
            for (int f = 0; f < 2; f++) {
                mma16816(acc[f][2*jp],   ah[f], bh);
                mma16816(acc[f][2*jp],   ah[f], bl);
                mma16816(acc[f][2*jp+1], ah[f], bh+2);
                mma16816(acc[f][2*jp+1], ah[f], bl+2);
            }
        }
    }
}

#define STAGE_HALVES (3*128*72)
#define GEMM_SMEM_BYTES (2*STAGE_HALVES*2)      // 110592 B
#define BD_SMEM_BYTES (STAGE_HALVES*2)

// =====================================================================
// QKV projection
// =====================================================================
__device__ __forceinline__ void qkv_load_stage(__half* S, int r0, int c0, int k0, int t)
{
    __half* Ah = S;
    __half* Bh = Ah + 128*72;
    __half* Bl = Bh + 128*72;
#pragma unroll
    for (int i = 0; i < 4; i++) {
        int fid = t + i*256;
        int row = fid >> 3, c8 = fid & 7;
        cp16(&Ah[row*72 + c8*8], &g_Inh [(size_t)(r0+row)*512 + k0 + c8*8]);
        cp16(&Bh[row*72 + c8*8], &g_WqTh[(size_t)(c0+row)*512 + k0 + c8*8]);
        cp16(&Bl[row*72 + c8*8], &g_WqTl[(size_t)(c0+row)*512 + k0 + c8*8]);
    }
}

__global__ __launch_bounds__(256) void qkv_kernel(
    const float* __restrict__ u_emb, const float* __restrict__ v_emb)
{
    extern __shared__ __half smh[];
    int t = threadIdx.x, lane = t & 31, wid = t >> 5;
    int wm = (wid & 3)*32, wn = (wid >> 2)*64;
    int r0 = blockIdx.y*128, c0 = blockIdx.x*128;
    int which0 = c0 >> 9;
    if (which0 == 0 && (r0 & 1023) < MEML) return;

    float acc[2][8][4];
#pragma unroll
    for (int f = 0; f < 2; f++)
#pragma unroll
        for (int j = 0; j < 8; j++)
#pragma unroll
            for (int e = 0; e < 4; e++) acc[f][j][e] = 0.f;

    qkv_load_stage(smh, r0, c0, 0, t);
    cp_commit();
#pragma unroll
    for (int it = 0; it < 8; it++) {
        __half* cur = smh + (it & 1)*STAGE_HALVES;
        cp_wait<0>();
        __syncthreads();
        if (it < 7) {
            qkv_load_stage(smh + ((it+1) & 1)*STAGE_HALVES, r0, c0, (it+1)*64, t);
            cp_commit();
        }
        gemm_block_k64_A1(cur, cur + 128*72, cur + 2*128*72, lane, wm, wn, acc);
    }

    if (which0 == 2) {
        __syncthreads();
        __half* Th = smh;                 // [col 128][row 128] stride 136
        __half* Tl = smh + 128*136;
#pragma unroll
        for (int f = 0; f < 2; f++)
#pragma unroll
            for (int j = 0; j < 8; j++)
#pragma unroll
                for (int ii = 0; ii < 2; ii++) {
                    int row = wm + f*16 + (lane >> 2) + ii*8;
                    int colL = wn + j*8 + 2*(lane & 3);
                    float v0 = acc[f][j][2*ii], v1 = acc[f][j][2*ii+1];
                    __half h0, l0, h1, l1;
                    split1h(v0, h0, l0); split1h(v1, h1, l1);
                    Th[colL*136 + row] = h0; Th[(colL+1)*136 + row] = h1;
                    Tl[colL*136 + row] = l0; Tl[(colL+1)*136 + row] = l1;
                }
        __syncthreads();
        int b = r0 >> 10, posbase = r0 & 1023;
        int cpr = c0 - 1024;
#pragma unroll
        for (int i = 0; i < 8; i++) {
            int idx = t + i*256;
            int col = idx >> 4, u8 = idx & 15;
            int cc = cpr + col;
            int h = cc >> 6, d = cc & 63;
            size_t o = (((size_t)(b*NH + h))*DH + d)*TOT + posbase + u8*8;
            *(uint4*)&g_VTh[o] = *(const uint4*)&Th[col*136 + u8*8];
            *(uint4*)&g_VTl[o] = *(const uint4*)&Tl[col*136 + u8*8];
        }
        return;
    }

#pragma unroll
    for (int f = 0; f < 2; f++)
#pragma unroll
        for (int j = 0; j < 8; j++)
#pragma unroll
            for (int ii = 0; ii < 2; ii++) {
                int gr = r0 + wm + f*16 + (lane >> 2) + ii*8;
                int gc = c0 + wn + j*8 + 2*(lane & 3);
                float v0 = acc[f][j][2*ii], v1 = acc[f][j][2*ii+1];
                int b = gr >> 10, pos = gr & 1023;
                int cc = gc & 511;
                int h = cc >> 6, d = cc & 63;
                int bh = b*NH + h;
                if (which0 == 1) {
                    __half2 hh, ll; split2h(v0, v1, hh, ll);
                    size_t idx = ((size_t)bh*TOT + pos)*DH + d;
                    *(__half2*)&g_Kh[idx] = hh; *(__half2*)&g_Kl[idx] = ll;
                } else if (pos >= MEML) {
                    int n = pos - MEML;
                    size_t idx = ((size_t)bh*SEQL + n)*DH + d;
                    *(__half2*)&g_QUh[idx] = __floats2half2_rn(v0 + u_emb[d], v1 + u_emb[d+1]);
                    *(__half2*)&g_QVh[idx] = __floats2half2_rn(v0 + v_emb[d], v1 + v_emb[d+1]);
                }
            }
}

// =====================================================================
// bd: A = QV hi, B = Krel split. Shift done in SMEM; coalesced fp16 stores.
// smem T[128][136]: T[row][c] holds value for global m = m_lo(row) + c,
// where m_lo(row) = MEML + n0 + row - s0 - 127 (reversed-column store).
// =====================================================================
__global__ __launch_bounds__(256) void bd_kernel()
{
    extern __shared__ __half smh[];
    __half* Ah = smh;
    __half* Bh = Ah + 128*72;
    __half* Bl = Bh + 128*72;
    int t = threadIdx.x, lane = t & 31, wid = t >> 5;
    int wm = (wid & 3)*32, wn = (wid >> 2)*64;
    int bh = blockIdx.z, h = bh & 7;
    int n0 = blockIdx.y*128, s0 = blockIdx.x*128;
    if (s0 > MEML + n0 + 127) return;

    float acc[2][8][4];
#pragma unroll
    for (int f = 0; f < 2; f++)
#pragma unroll
        for (int j = 0; j < 8; j++)
#pragma unroll
            for (int e = 0; e < 4; e++) acc[f][j][e] = 0.f;

#pragma unroll
    for (int i = 0; i < 4; i++) {
        int fid = t + i*256;
        int row = fid >> 3, c8 = fid & 7;
        cp16(&Ah[row*72 + c8*8], &g_QVh[((size_t)bh*SEQL + n0 + row)*DH + c8*8]);
        cp16(&Bh[row*72 + c8*8], &g_Krelh[((size_t)h*CTXL + s0 + row)*DH + c8*8]);
        cp16(&Bl[row*72 + c8*8], &g_Krell[((size_t)h*CTXL + s0 + row)*DH + c8*8]);
    }
    cp_commit();
    cp_wait<0>();
    __syncthreads();
    gemm_block_k64_A1(Ah, Bh, Bl, lane, wm, wn, acc);

    __syncthreads();          // done with A/B smem; reuse as shift tile
    __half* T = smh;          // [128][136]
#pragma unroll
    for (int f = 0; f < 2; f++)
#pragma unroll
        for (int j = 0; j < 8; j++)
#pragma unroll
            for (int ii = 0; ii < 2; ii++) {
                int nl = wm + f*16 + (lane >> 2) + ii*8;
                int sl = wn + j*8 + 2*(lane & 3);
                // value(sl) -> col 127-sl; value(sl+1) -> col 126-sl
                *(__half2*)&T[nl*136 + (126 - sl)] =
                    __floats2half2_rn(acc[f][j][2*ii+1], acc[f][j][2*ii]);
            }
    __syncthreads();

    // writeback: warp wid handles rows wid, wid+8, ...
    for (int r = wid; r < 128; r += 8) {
        int n_g = n0 + r;
        int m_hi = MEML + n_g - s0;
        if (m_hi < 0) continue;
        int m_lo = m_hi - 127;
        int lo = m_lo < 0 ? 0 : m_lo;
        __half* grow = g_BDs + ((size_t)bh*SEQL + n_g)*TOT;
        const __half* Tr = T + r*136;
        if (lane == 0) {
            if (lo & 1)       grow[lo]   = Tr[lo - m_lo];      // odd head
            if (!(m_hi & 1))  grow[m_hi] = Tr[m_hi - m_lo];    // even tail
        }
        int lo2 = (lo + 1) & ~1;                               // first even m
        for (int m = lo2 + 2*lane; m + 1 <= m_hi; m += 64) {
            __half2 v = __halves2half2(Tr[m - m_lo], Tr[m - m_lo + 1]);
            *(__half2*)&grow[m] = v;
        }
    }
}

// =====================================================================
// attn: split-KV flash attention (2 splits), fp16 BD reads
// =====================================================================
#define ATTN_SMEM_BYTES (6*64*72*2)   // 55296 B

__device__ __forceinline__ void attn_load_kv(
    __half* kv, int bh, int m0, int t)
{
    __half* Kh = kv;
    __half* Kl = Kh + 64*72;
    __half* Vh = Kl + 64*72;
    __half* Vl = Vh + 64*72;
#pragma unroll
    for (int i = 0; i < 4; i++) {
        int fid = t + i*128;
        int row = fid >> 3, c8 = fid & 7;
        cp16(&Kh[row*72 + c8*8], &g_Kh[((size_t)bh*TOT + m0 + row)*DH + c8*8]);
        cp16(&Kl[row*72 + c8*8], &g_Kl[((size_t)bh*TOT + m0 + row)*DH + c8*8]);
        cp16(&Vh[row*72 + c8*8], &g_VTh[((size_t)bh*DH + row)*TOT + m0 + c8*8]);
        cp16(&Vl[row*72 + c8*8], &g_VTl[((size_t)bh*DH + row)*TOT + m0 + c8*8]);
    }
}

__global__ __launch_bounds__(128) void attn_kernel()
{
    extern __shared__ __half smh[];
    __half* Qh = smh;
    __half* Ph = Qh + 64*72;
    __half* KV = Ph + 64*72;
    __half* Kh = KV;
    __half* Kl = Kh + 64*72;
    __half* Vh = Kl + 64*72;
    __half* Vl = Vh + 64*72;

    int t = threadIdx.x, lane = t & 31, wq = t >> 5;
    int bh = blockIdx.y;
    int n0 = blockIdx.x * 64;
    int split = blockIdx.z;

    int nt = (MEML + n0 + 63)/64 + 1;
    int t0 = split ? nt/2 : 0;
    int t1 = split ? nt : nt/2;

    int arow = (lane & 7) + ((lane >> 3) & 1)*8;
    int acol = (lane >> 4)*8;
    int brow = (lane & 7) + (lane >> 4)*8;
    int bcol = ((lane >> 3) & 1)*8;

#pragma unroll
    for (int i = 0; i < 4; i++) {
        int fid = t + i*128;
        int row = fid >> 3, c8 = fid & 7;
        cp16(&Qh[row*72 + c8*8], &g_QUh[((size_t)bh*SEQL + n0 + row)*DH + c8*8]);
    }
    attn_load_kv(KV, bh, t0*64, t);
    cp_commit();

    float O[8][4];
#pragma unroll
    for (int j = 0; j < 8; j++)
#pragma unroll
        for (int e = 0; e < 4; e++) O[j][e] = 0.f;
    float M[2] = {-1e30f, -1e30f}, L[2] = {0.f, 0.f};

    int rl0 = wq*16 + (lane >> 2);
    int c0j = 2*(lane & 3);
    const __half* BDr0 = g_BDs + ((size_t)bh*SEQL + (n0 + rl0))*TOT;
    const __half* BDr1 = BDr0 + 8*(size_t)TOT;
    int lim0 = MEML + n0 + rl0, lim1 = lim0 + 8;

    for (int tile = t0; tile < t1; tile++) {
        int m0 = tile*64;
        cp_wait<0>();
        __syncthreads();

        float2 bdv[2][8];
#pragma unroll
        for (int j = 0; j < 8; j++) {
            int m = m0 + j*8 + c0j;
            bdv[0][j] = __half22float2(*(const __half2*)&BDr0[m]);
            bdv[1][j] = __half22float2(*(const __half2*)&BDr1[m]);
        }

        // ---- S = Q . K^T ----
        float S[8][4];
#pragma unroll
        for (int j = 0; j < 8; j++)
#pragma unroll
            for (int e = 0; e < 4; e++) S[j][e] = 0.f;
#pragma unroll
        for (int kb = 0; kb < 64; kb += 16) {
            unsigned ah[4];
            ldsm4(ah, &Qh[(wq*16 + arow)*72 + kb + acol]);
#pragma unroll
            for (int jp = 0; jp < 4; jp++) {
                unsigned bhf[4], blf[4];
                ldsm4(bhf, &Kh[(jp*16 + brow)*72 + kb + bcol]);
                ldsm4(blf, &Kl[(jp*16 + brow)*72 + kb + bcol]);
                mma16816(S[2*jp],   ah, bhf);
                mma16816(S[2*jp],   ah, blf);
                mma16816(S[2*jp+1], ah, bhf+2);
                mma16816(S[2*jp+1], ah, blf+2);
            }
        }

        // ---- BD add + mask + online softmax ----
#pragma unroll
        for (int i = 0; i < 2; i++) {
            int lim = i ? lim1 : lim0;
            float mx = -1e30f;
#pragma unroll
            for (int j = 0; j < 8; j++) {
                int m = m0 + j*8 + c0j;
                float v0 = (m   <= lim) ? (S[j][2*i]   + bdv[i][j].x)*0.125f : -1e30f;
                float v1 = (m+1 <= lim) ? (S[j][2*i+1] + bdv[i][j].y)*0.125f : -1e30f;
                S[j][2*i] = v0; S[j][2*i+1] = v1;
                mx = fmaxf(mx, fmaxf(v0, v1));
            }
            mx = fmaxf(mx, __shfl_xor_sync(0xffffffffu, mx, 1));
            mx = fmaxf(mx, __shfl_xor_sync(0xffffffffu, mx, 2));
            float Mn = fmaxf(M[i], mx);
            float alpha = __expf(M[i] - Mn);
            M[i] = Mn;
            float sum = 0.f;
            int rl = rl0 + 8*i;
#pragma unroll
            for (int j = 0; j < 8; j++) {
                float p0 = __expf(S[j][2*i]   - Mn);
                float p1 = __expf(S[j][2*i+1] - Mn);
                sum += p0 + p1;
                *(__half2*)&Ph[rl*72 + j*8 + c0j] = __floats2half2_rn(p0, p1);
                O[j][2*i] *= alpha; O[j][2*i+1] *= alpha;
            }
            sum += __shfl_xor_sync(0xffffffffu, sum, 1);
            sum += __shfl_xor_sync(0xffffffffu, sum, 2);
            L[i] = L[i]*alpha + sum;
        }
        __syncwarp();

        // ---- O += P . V ----
#pragma unroll
        for (int kb = 0; kb < 64; kb += 16) {
            unsigned ah[4];
            ldsm4(ah, &Ph[(wq*16 + arow)*72 + kb + acol]);
#pragma unroll
            for (int jp = 0; jp < 4; jp++) {
                unsigned bhf[4], blf[4];
                ldsm4(bhf, &Vh[(jp*16 + brow)*72 + kb + bcol]);
                ldsm4(blf, &Vl[(jp*16 + brow)*72 + kb + bcol]);
                mma16816(O[2*jp],   ah, bhf);
                mma16816(O[2*jp],   ah, blf);
                mma16816(O[2*jp+1], ah, bhf+2);
                mma16816(O[2*jp+1], ah, blf+2);
            }
        }

        __syncthreads();
        if (tile + 1 < t1) {
            attn_load_kv(KV, bh, (tile+1)*64, t);
            cp_commit();
        }
    }

    // ---- write unnormalized partials ----
    size_t pbase = (((size_t)split*64 + bh)*4 + (n0 >> 6))*64;
    float* Op = g_Opart + pbase*64;
#pragma unroll
    for (int i = 0; i < 2; i++) {
        int row = rl0 + 8*i;
        if ((lane & 3) == 0) {
            g_Mpart[pbase + row] = M[i];
            g_Lpart[pbase + row] = L[i];
        }
#pragma unroll
        for (int j = 0; j < 8; j++) {
            int col = j*8 + c0j;
            *(float2*)&Op[(size_t)row*64 + col] = make_float2(O[j][2*i], O[j][2*i+1]);
        }
    }
}

// =====================================================================
// attn_comb: merge 2 split-KV partials -> g_AOh
// =====================================================================
__global__ __launch_bounds__(256) void attn_comb_kernel()
{
    __shared__ float f0[64], f1[64];
    int t = threadIdx.x;
    int n4 = blockIdx.x;
    int bh = blockIdx.y;
    int b = bh >> 3, h = bh & 7;
    size_t p0 = (((size_t)0*64 + bh)*4 + n4)*64;
    size_t p1 = (((size_t)1*64 + bh)*4 + n4)*64;

    if (t < 64) {
        float M0 = g_Mpart[p0 + t], M1 = g_Mpart[p1 + t];
        float L0 = g_Lpart[p0 + t], L1 = g_Lpart[p1 + t];
        float Mn = fmaxf(M0, M1);
        float a0 = __expf(M0 - Mn), a1 = __expf(M1 - Mn);
        float L = L0*a0 + L1*a1;
        f0[t] = a0 / L;
        f1[t] = a1 / L;
    }
    __syncthreads();

    const float* O0 = g_Opart + p0*64;
    const float* O1 = g_Opart + p1*64;
#pragma unroll
    for (int k = 0; k < 8; k++) {
        int idx = t + k*256;
        int row = idx >> 5;
        int c2 = (idx & 31)*2;
        float2 a = *(const float2*)&O0[(size_t)row*64 + c2];
        float2 bpt = *(const float2*)&O1[(size_t)row*64 + c2];
        float o0 = a.x*f0[row] + bpt.x*f1[row];
        float o1 = a.y*f0[row] + bpt.y*f1[row];
        size_t oidx = ((size_t)(b*SEQL + n4*64 + row))*INNERD + h*DH + c2;
        *(__half2*)&g_AOh[oidx] = __floats2half2_rn(o0, o1);
    }
}

// =====================================================================
// out: A = AO hi, B = Wout split. 128x128 tile, double-buffered.
// =====================================================================
__device__ __forceinline__ void out_load_stage(__half* S, int r0, int c0, int k0, int t)
{
    __half* Ah = S;
    __half* Bh = Ah + 128*72;
    __half* Bl = Bh + 128*72;
#pragma unroll
    for (int i = 0; i < 4; i++) {
        int fid = t + i*256;
        int row = fid >> 3, c8 = fid & 7;
        cp16(&Ah[row*72 + c8*8], &g_AOh [(size_t)(r0+row)*512 + k0 + c8*8]);
        cp16(&Bh[row*72 + c8*8], &g_WoTh[(size_t)(c0+row)*512 + k0 + c8*8]);
        cp16(&Bl[row*72 + c8*8], &g_WoTl[(size_t)(c0+row)*512 + k0 + c8*8]);
    }
}

__global__ __launch_bounds__(256) void out_kernel(
    const float* __restrict__ bias, float* __restrict__ out)
{
    extern __shared__ __half smh[];
    int t = threadIdx.x, lane = t & 31, wid = t >> 5;
    int wm = (wid & 3)*32, wn = (wid >> 2)*64;
    int r0 = blockIdx.y*128, c0 = blockIdx.x*128;

    float acc[2][8][4];
#pragma unroll
    for (int f = 0; f < 2; f++)
#pragma unroll
        for (int j = 0; j < 8; j++)
#pragma unroll
            for (int e = 0; e < 4; e++) acc[f][j][e] = 0.f;

    out_load_stage(smh, r0, c0, 0, t);
    cp_commit();
#pragma unroll
    for (int it = 0; it < 8; it++) {
        __half* cur = smh + (it & 1)*STAGE_HALVES;
        cp_wait<0>();
        __syncthreads();
        if (it < 7) {
            out_load_stage(smh + ((it+1) & 1)*STAGE_HALVES, r0, c0, (it+1)*64, t);
            cp_commit();
        }
        gemm_block_k64_A1(cur, cur + 128*72, cur + 2*128*72, lane, wm, wn, acc);
    }

#pragma unroll
    for (int f = 0; f < 2; f++)
#pragma unroll
        for (int j = 0; j < 8; j++)
#pragma unroll
            for (int ii = 0; ii < 2; ii++) {
                int gr = r0 + wm + f*16 + (lane >> 2) + ii*8;
                int gc = c0 + wn + j*8 + 2*(lane & 3);
                *(float2*)&out[(size_t)gr*DIMM + gc] =
                    make_float2(acc[f][j][2*ii] + bias[gc], acc[f][j][2*ii+1] + bias[gc+1]);
            }
}

// =====================================================================
extern "C" void kernel_launch(void* const* d_in, const int* in_sizes, int n_in,
                              void* d_out, int out_size)
{
    const float* x      = (const float*)d_in[0];
    const float* memory = (const float*)d_in[1];
    const float* Wqkv   = (const float*)d_in[2];
    const float* Wrel   = (const float*)d_in[3];
    const float* Wout   = (const float*)d_in[4];
    const float* bout   = (const float*)d_in[5];
    const float* u_emb  = (const float*)d_in[6];
    const float* v_emb  = (const float*)d_in[7];
    float* out = (float*)d_out;
    (void)in_sizes; (void)n_in; (void)out_size;

    cudaFuncSetAttribute(qkv_kernel,  cudaFuncAttributeMaxDynamicSharedMemorySize, GEMM_SMEM_BYTES);
    cudaFuncSetAttribute(bd_kernel,   cudaFuncAttributeMaxDynamicSharedMemorySize, BD_SMEM_BYTES);
    cudaFuncSetAttribute(out_kernel,  cudaFuncAttributeMaxDynamicSharedMemorySize, GEMM_SMEM_BYTES);
    cudaFuncSetAttribute(attn_kernel, cudaFuncAttributeMaxDynamicSharedMemorySize, ATTN_SMEM_BYTES);

    pre_in_kernel<<<8192*512/4/256, 256>>>(x, memory);
    prep_small_kernel<<<384, 256>>>(Wqkv, Wout, Wrel);
    qkv_kernel<<<dim3(1536/128, 8192/128), 256, GEMM_SMEM_BYTES>>>(u_emb, v_emb);
    bd_kernel<<<dim3(CTXL/128, SEQL/128, BB*NH), 256, BD_SMEM_BYTES>>>();
    attn_kernel<<<dim3(SEQL/64, BB*NH, 2), 128, ATTN_SMEM_BYTES>>>();
    attn_comb_kernel<<<dim3(SEQL/64, BB*NH), 256>>>();
    out_kernel<<<dim3(DIMM/128, 2048/128), 256, GEMM_SMEM_BYTES>>>(bout, out);
}